// round 1
// baseline (speedup 1.0000x reference)
#include <cuda_runtime.h>
#include <cuda_bf16.h>
#include <math.h>

#define BATCH 4
#define SEQ 4096
#define CDIM 1024
#define HDIM 64
#define MROWS (BATCH * SEQ)   // 16384

// Scratch for projected q/k/v (no cudaMalloc allowed)
__device__ float g_q[(size_t)MROWS * HDIM];
__device__ float g_k[(size_t)MROWS * HDIM];
__device__ float g_v[(size_t)MROWS * HDIM];

// ---------------------------------------------------------------------------
// Projection: out = x @ W   (x: [M, 1024], W: [1024, 64])
// 64x64 tile per block; blockIdx.y in {0,1,2} selects q/k/v.
// ---------------------------------------------------------------------------
__global__ __launch_bounds__(256) void proj_kernel(
    const float* __restrict__ x,
    const float* __restrict__ Wq,
    const float* __restrict__ Wk,
    const float* __restrict__ Wv)
{
    __shared__ float As[64 * 64];
    __shared__ float Bs[64 * 64];

    const int which = blockIdx.y;
    const float* __restrict__ W = (which == 0) ? Wq : (which == 1) ? Wk : Wv;
    float* __restrict__ out = (which == 0) ? g_q : (which == 1) ? g_k : g_v;

    const int tid = threadIdx.x;
    const int tx = tid & 15;        // 16 col groups of 4
    const int ty = tid >> 4;        // 16 row groups of 4
    const int row0 = blockIdx.x * 64;

    float acc[4][4];
#pragma unroll
    for (int i = 0; i < 4; i++)
#pragma unroll
        for (int j = 0; j < 4; j++) acc[i][j] = 0.0f;

    for (int kc = 0; kc < CDIM; kc += 64) {
        // load tiles: 1024 float4 each, 256 threads x 4
#pragma unroll
        for (int i = 0; i < 4; i++) {
            int idx = tid + i * 256;        // 0..1023
            int r = idx >> 4;               // row 0..63
            int c4 = idx & 15;              // float4 col 0..15
            float4 xa = *(const float4*)&x[(size_t)(row0 + r) * CDIM + kc + c4 * 4];
            *(float4*)&As[r * 64 + c4 * 4] = xa;
            float4 wb = *(const float4*)&W[(size_t)(kc + r) * HDIM + c4 * 4];
            *(float4*)&Bs[r * 64 + c4 * 4] = wb;
        }
        __syncthreads();

#pragma unroll
        for (int k = 0; k < 64; k++) {
            float a[4], b[4];
#pragma unroll
            for (int i = 0; i < 4; i++) a[i] = As[(ty * 4 + i) * 64 + k];
#pragma unroll
            for (int j = 0; j < 4; j++) b[j] = Bs[k * 64 + tx * 4 + j];
#pragma unroll
            for (int i = 0; i < 4; i++)
#pragma unroll
                for (int j = 0; j < 4; j++) acc[i][j] += a[i] * b[j];
        }
        __syncthreads();
    }

#pragma unroll
    for (int i = 0; i < 4; i++) {
        float4 o = make_float4(acc[i][0], acc[i][1], acc[i][2], acc[i][3]);
        *(float4*)&out[(size_t)(row0 + ty * 4 + i) * HDIM + tx * 4] = o;
    }
}

// ---------------------------------------------------------------------------
// Flash attention (fp32, causal). One CTA per 64-query tile per batch.
// 8 warps; warp w owns query rows w*8 .. w*8+7; lane owns cols {lane, lane+32}.
// ---------------------------------------------------------------------------
__global__ __launch_bounds__(256) void attn_kernel(float* __restrict__ out)
{
    extern __shared__ float sm[];
    float* Qs = sm;                 // 64 x 64
    float* Ks = Qs + 64 * 64;       // 64 x 65 (padded: conflict-free column reads)
    float* Vs = Ks + 64 * 65;       // 64 x 64
    float* Ps = Vs + 64 * 64;       // 64 x 64

    const int b = blockIdx.y;
    const int qt = blockIdx.x;
    const int tid = threadIdx.x;
    const int warp = tid >> 5;
    const int lane = tid & 31;
    const int r0 = warp * 8;

    const float* __restrict__ qb = g_q + ((size_t)b * SEQ + qt * 64) * HDIM;
    const float* __restrict__ kbase = g_k + (size_t)b * SEQ * HDIM;
    const float* __restrict__ vbase = g_v + (size_t)b * SEQ * HDIM;

    // load Q tile (64x64 = 1024 float4)
#pragma unroll
    for (int i = 0; i < 4; i++) {
        int idx = tid + i * 256;
        int r = idx >> 4;
        int c4 = idx & 15;
        *(float4*)&Qs[r * 64 + c4 * 4] =
            *(const float4*)&qb[(size_t)r * HDIM + c4 * 4];
    }

    float m_r[8], l_r[8], o0[8], o1[8];
#pragma unroll
    for (int r = 0; r < 8; r++) {
        m_r[r] = -INFINITY; l_r[r] = 0.0f; o0[r] = 0.0f; o1[r] = 0.0f;
    }

    for (int j = 0; j <= qt; j++) {
        __syncthreads();   // prior-iter readers done (also covers Q-load on iter 0)
        const float* kb = kbase + (size_t)j * 64 * HDIM;
        const float* vb = vbase + (size_t)j * 64 * HDIM;
#pragma unroll
        for (int i = 0; i < 4; i++) {
            int idx = tid + i * 256;
            int r = idx >> 4;
            int c4 = idx & 15;
            float4 kv = *(const float4*)&kb[(size_t)r * HDIM + c4 * 4];
            Ks[r * 65 + c4 * 4 + 0] = kv.x;
            Ks[r * 65 + c4 * 4 + 1] = kv.y;
            Ks[r * 65 + c4 * 4 + 2] = kv.z;
            Ks[r * 65 + c4 * 4 + 3] = kv.w;
            *(float4*)&Vs[r * 64 + c4 * 4] =
                *(const float4*)&vb[(size_t)r * HDIM + c4 * 4];
        }
        __syncthreads();

        // S = Q K^T for this warp's 8 rows, cols lane & lane+32
        float s0[8], s1[8];
#pragma unroll
        for (int r = 0; r < 8; r++) { s0[r] = 0.0f; s1[r] = 0.0f; }
#pragma unroll 8
        for (int kk = 0; kk < 64; kk++) {
            float kb0 = Ks[lane * 65 + kk];
            float kb1 = Ks[(lane + 32) * 65 + kk];
#pragma unroll
            for (int r = 0; r < 8; r++) {
                float qa = Qs[(r0 + r) * 64 + kk];
                s0[r] += qa * kb0;
                s1[r] += qa * kb1;
            }
        }

        const bool diag = (j == qt);
#pragma unroll
        for (int r = 0; r < 8; r++) {
            float v0 = s0[r] * 0.125f;   // 1/sqrt(64)
            float v1 = s1[r] * 0.125f;
            if (diag) {
                if (lane > r0 + r)      v0 = -1e30f;
                if (lane + 32 > r0 + r) v1 = -1e30f;
            }
            float mx = fmaxf(v0, v1);
#pragma unroll
            for (int off = 16; off > 0; off >>= 1)
                mx = fmaxf(mx, __shfl_xor_sync(0xffffffffu, mx, off));
            float mnew = fmaxf(m_r[r], mx);
            float p0 = __expf(v0 - mnew);
            float p1 = __expf(v1 - mnew);
            float alpha = __expf(m_r[r] - mnew);
            float psum = p0 + p1;
#pragma unroll
            for (int off = 16; off > 0; off >>= 1)
                psum += __shfl_xor_sync(0xffffffffu, psum, off);
            l_r[r] = l_r[r] * alpha + psum;
            m_r[r] = mnew;
            o0[r] *= alpha;
            o1[r] *= alpha;
            Ps[(r0 + r) * 64 + lane] = p0;
            Ps[(r0 + r) * 64 + lane + 32] = p1;
        }
        __syncwarp();   // P written/read within the same warp only

        // O += P @ V   (this warp's 8 rows; lane owns h = lane, lane+32)
#pragma unroll 4
        for (int s = 0; s < 64; s++) {
            float v0 = Vs[s * 64 + lane];
            float v1 = Vs[s * 64 + lane + 32];
#pragma unroll
            for (int r = 0; r < 8; r++) {
                float p = Ps[(r0 + r) * 64 + s];
                o0[r] += p * v0;
                o1[r] += p * v1;
            }
        }
    }

    float* ob = out + ((size_t)b * SEQ + qt * 64) * HDIM;
#pragma unroll
    for (int r = 0; r < 8; r++) {
        float inv = 1.0f / l_r[r];
        ob[(size_t)(r0 + r) * HDIM + lane]      = o0[r] * inv;
        ob[(size_t)(r0 + r) * HDIM + lane + 32] = o1[r] * inv;
    }
}

// ---------------------------------------------------------------------------
extern "C" void kernel_launch(void* const* d_in, const int* in_sizes, int n_in,
                              void* d_out, int out_size)
{
    const float* x  = (const float*)d_in[0];
    const float* Wk = (const float*)d_in[1];
    const float* Wq = (const float*)d_in[2];
    const float* Wv = (const float*)d_in[3];
    float* out = (float*)d_out;

    dim3 pgrid(MROWS / 64, 3);
    proj_kernel<<<pgrid, 256>>>(x, Wq, Wk, Wv);

    const int smem = (64 * 64 + 64 * 65 + 64 * 64 + 64 * 64) * (int)sizeof(float);
    static int attr_set = 0;
    // idempotent + capture-safe (not a stream op); setting every call is fine
    cudaFuncSetAttribute(attn_kernel, cudaFuncAttributeMaxDynamicSharedMemorySize, smem);
    (void)attr_set;

    dim3 agrid(SEQ / 64, BATCH);
    attn_kernel<<<agrid, 256, smem>>>(out);
}

// round 2
// speedup vs baseline: 2.4954x; 2.4954x over previous
#include <cuda_runtime.h>
#include <cuda_bf16.h>
#include <math.h>

#define BATCH 4
#define SEQ 4096
#define CDIM 1024
#define HDIM 64
#define MROWS (BATCH * SEQ)   // 16384

// Scratch for projected q/k/v (no cudaMalloc allowed)
__device__ float g_q[(size_t)MROWS * HDIM];
__device__ float g_k[(size_t)MROWS * HDIM];
__device__ float g_v[(size_t)MROWS * HDIM];

// ---------------------------------------------------------------------------
// Projection: out = x @ W   (x: [M, 1024], W: [1024, 64])
// BM=128, BN=64, BK=32; 256 threads; per-thread 8x4 outputs.
// blockIdx.y in {0,1,2} selects q/k/v.
// ---------------------------------------------------------------------------
#define AS_STRIDE 36   // 128 rows x 36 (pad: 16B-aligned rows, broadcast-friendly)

__global__ __launch_bounds__(256) void proj_kernel(
    const float* __restrict__ x,
    const float* __restrict__ Wq,
    const float* __restrict__ Wk,
    const float* __restrict__ Wv)
{
    __shared__ float As[128 * AS_STRIDE];
    __shared__ float Bs[32 * 64];

    const int which = blockIdx.y;
    const float* __restrict__ W = (which == 0) ? Wq : (which == 1) ? Wk : Wv;
    float* __restrict__ out = (which == 0) ? g_q : (which == 1) ? g_k : g_v;

    const int tid = threadIdx.x;
    const int tc = tid & 15;        // col group: 4 cols each -> 64
    const int tr = tid >> 4;        // row group: 8 rows each -> 128
    const int row0 = blockIdx.x * 128;

    float acc[8][4];
#pragma unroll
    for (int i = 0; i < 8; i++)
#pragma unroll
        for (int j = 0; j < 4; j++) acc[i][j] = 0.0f;

    for (int kc = 0; kc < CDIM; kc += 32) {
        // As: 128x32 floats = 1024 float4, 4 per thread
#pragma unroll
        for (int i = 0; i < 4; i++) {
            int idx = tid + i * 256;        // 0..1023
            int r = idx >> 3;               // row 0..127
            int c4 = idx & 7;               // float4 col 0..7
            float4 v = *(const float4*)&x[(size_t)(row0 + r) * CDIM + kc + c4 * 4];
            *(float4*)&As[r * AS_STRIDE + c4 * 4] = v;
        }
        // Bs: 32x64 floats = 512 float4, 2 per thread
#pragma unroll
        for (int i = 0; i < 2; i++) {
            int idx = tid + i * 256;        // 0..511
            int r = idx >> 4;               // row 0..31
            int c4 = idx & 15;              // float4 col 0..15
            *(float4*)&Bs[r * 64 + c4 * 4] =
                *(const float4*)&W[(size_t)(kc + r) * HDIM + c4 * 4];
        }
        __syncthreads();

#pragma unroll
        for (int k = 0; k < 32; k++) {
            float a[8];
#pragma unroll
            for (int i = 0; i < 8; i++) a[i] = As[(tr * 8 + i) * AS_STRIDE + k];
            float4 bv = *(const float4*)&Bs[k * 64 + tc * 4];
            float b[4] = {bv.x, bv.y, bv.z, bv.w};
#pragma unroll
            for (int i = 0; i < 8; i++)
#pragma unroll
                for (int j = 0; j < 4; j++) acc[i][j] += a[i] * b[j];
        }
        __syncthreads();
    }

#pragma unroll
    for (int i = 0; i < 8; i++) {
        float4 o = make_float4(acc[i][0], acc[i][1], acc[i][2], acc[i][3]);
        *(float4*)&out[(size_t)(row0 + tr * 8 + i) * HDIM + tc * 4] = o;
    }
}

// ---------------------------------------------------------------------------
// Flash attention (fp32, causal). 32-query tiles; each CTA handles the pair
// (tile p, tile 127-p) sequentially -> constant work per CTA (~64.5 key blocks).
// 256 threads = 8 warps; warp owns 4 query rows; lane owns key cols {lane, lane+32}.
// ---------------------------------------------------------------------------
#define KS_STRIDE 68   // 64 keys x 68 floats (16B-aligned rows, conflict-free LDS.128)

__device__ __forceinline__ void attn_tile(
    int b, int t, float* __restrict__ out,
    float* Qs, float* Ks, float* Vs, float* Ps)
{
    const int tid = threadIdx.x;
    const int warp = tid >> 5;
    const int lane = tid & 31;
    const int wr = warp * 4;          // warp's first query row in tile
    const int qr0 = t * 32;

    const float* __restrict__ qb = g_q + ((size_t)b * SEQ + qr0) * HDIM;
    const float* __restrict__ kbase = g_k + (size_t)b * SEQ * HDIM;
    const float* __restrict__ vbase = g_v + (size_t)b * SEQ * HDIM;

    __syncthreads();   // previous phase done reading Qs
    // Q tile: 32x64 = 512 float4, 2 per thread
#pragma unroll
    for (int i = 0; i < 2; i++) {
        int idx = tid + i * 256;
        int r = idx >> 4;
        int c4 = idx & 15;
        *(float4*)&Qs[r * HDIM + c4 * 4] =
            *(const float4*)&qb[(size_t)r * HDIM + c4 * 4];
    }

    float m4[4], l4[4], o0[4], o1[4];
#pragma unroll
    for (int r = 0; r < 4; r++) {
        m4[r] = -INFINITY; l4[r] = 0.0f; o0[r] = 0.0f; o1[r] = 0.0f;
    }

    const int nkb = t / 2 + 1;
    for (int kb = 0; kb < nkb; kb++) {
        __syncthreads();
        const float* kp = kbase + (size_t)(kb * 64) * HDIM;
        const float* vp = vbase + (size_t)(kb * 64) * HDIM;
        // K,V tiles: 64x64 = 1024 float4 each, 4 per thread each
#pragma unroll
        for (int i = 0; i < 4; i++) {
            int idx = tid + i * 256;
            int r = idx >> 4;
            int c4 = idx & 15;
            *(float4*)&Ks[r * KS_STRIDE + c4 * 4] =
                *(const float4*)&kp[(size_t)r * HDIM + c4 * 4];
            *(float4*)&Vs[r * HDIM + c4 * 4] =
                *(const float4*)&vp[(size_t)r * HDIM + c4 * 4];
        }
        __syncthreads();

        // S = Q K^T : 4 rows x 2 cols per thread, vectorized over k
        float s0[4] = {0.f, 0.f, 0.f, 0.f};
        float s1[4] = {0.f, 0.f, 0.f, 0.f};
#pragma unroll
        for (int kk = 0; kk < HDIM; kk += 4) {
            float4 k0 = *(const float4*)&Ks[lane * KS_STRIDE + kk];
            float4 k1 = *(const float4*)&Ks[(lane + 32) * KS_STRIDE + kk];
#pragma unroll
            for (int r = 0; r < 4; r++) {
                float4 q = *(const float4*)&Qs[(wr + r) * HDIM + kk];
                s0[r] += q.x * k0.x + q.y * k0.y + q.z * k0.z + q.w * k0.w;
                s1[r] += q.x * k1.x + q.y * k1.y + q.z * k1.z + q.w * k1.w;
            }
        }

        // online softmax
        const bool maskb = (kb == nkb - 1);
#pragma unroll
        for (int r = 0; r < 4; r++) {
            const int rq = qr0 + wr + r;
            float v0 = s0[r] * 0.125f;   // 1/sqrt(64)
            float v1 = s1[r] * 0.125f;
            if (maskb) {
                int kg = kb * 64 + lane;
                if (kg > rq)      v0 = -1e30f;
                if (kg + 32 > rq) v1 = -1e30f;
            }
            float mx = fmaxf(v0, v1);
#pragma unroll
            for (int off = 16; off > 0; off >>= 1)
                mx = fmaxf(mx, __shfl_xor_sync(0xffffffffu, mx, off));
            float mnew = fmaxf(m4[r], mx);
            float p0 = __expf(v0 - mnew);
            float p1 = __expf(v1 - mnew);
            float alpha = __expf(m4[r] - mnew);
            float ps = p0 + p1;
#pragma unroll
            for (int off = 16; off > 0; off >>= 1)
                ps += __shfl_xor_sync(0xffffffffu, ps, off);
            l4[r] = l4[r] * alpha + ps;
            m4[r] = mnew;
            o0[r] *= alpha;
            o1[r] *= alpha;
            Ps[(wr + r) * HDIM + lane] = p0;
            Ps[(wr + r) * HDIM + lane + 32] = p1;
        }
        __syncwarp();   // Ps written/read within this warp only

        // O += P @ V : p loads are warp-broadcast float4s
#pragma unroll
        for (int s = 0; s < 64; s += 4) {
            float pr[4][4];
#pragma unroll
            for (int r = 0; r < 4; r++) {
                float4 p4 = *(const float4*)&Ps[(wr + r) * HDIM + s];
                pr[r][0] = p4.x; pr[r][1] = p4.y; pr[r][2] = p4.z; pr[r][3] = p4.w;
            }
#pragma unroll
            for (int u = 0; u < 4; u++) {
                float v0v = Vs[(s + u) * HDIM + lane];
                float v1v = Vs[(s + u) * HDIM + lane + 32];
#pragma unroll
                for (int r = 0; r < 4; r++) {
                    o0[r] += pr[r][u] * v0v;
                    o1[r] += pr[r][u] * v1v;
                }
            }
        }
    }

    float* ob = out + ((size_t)b * SEQ + qr0) * HDIM;
#pragma unroll
    for (int r = 0; r < 4; r++) {
        float inv = 1.0f / l4[r];
        ob[(size_t)(wr + r) * HDIM + lane]      = o0[r] * inv;
        ob[(size_t)(wr + r) * HDIM + lane + 32] = o1[r] * inv;
    }
}

__global__ __launch_bounds__(256) void attn_kernel(float* __restrict__ out)
{
    extern __shared__ float sm[];
    float* Qs = sm;                       // 32 x 64
    float* Ks = Qs + 32 * HDIM;           // 64 x 68
    float* Vs = Ks + 64 * KS_STRIDE;      // 64 x 64
    float* Ps = Vs + 64 * HDIM;           // 32 x 64

    const int b = blockIdx.y;
    const int pair = blockIdx.x;          // 0..63

    attn_tile(b, pair, out, Qs, Ks, Vs, Ps);
    attn_tile(b, 127 - pair, out, Qs, Ks, Vs, Ps);
}

// ---------------------------------------------------------------------------
extern "C" void kernel_launch(void* const* d_in, const int* in_sizes, int n_in,
                              void* d_out, int out_size)
{
    const float* x  = (const float*)d_in[0];
    const float* Wk = (const float*)d_in[1];
    const float* Wq = (const float*)d_in[2];
    const float* Wv = (const float*)d_in[3];
    float* out = (float*)d_out;

    dim3 pgrid(MROWS / 128, 3);
    proj_kernel<<<pgrid, 256>>>(x, Wq, Wk, Wv);

    const int smem = (32 * HDIM + 64 * KS_STRIDE + 64 * HDIM + 32 * HDIM) * (int)sizeof(float);
    cudaFuncSetAttribute(attn_kernel, cudaFuncAttributeMaxDynamicSharedMemorySize, smem);

    dim3 agrid(64, BATCH);
    attn_kernel<<<agrid, 256, smem>>>(out);
}